// round 16
// baseline (speedup 1.0000x reference)
#include <cuda_runtime.h>
#include <cuda_bf16.h>
#include <cstdint>

// Gather: out[i, y, x, c] = logits[i * N_SP + segments[i, y, x], c]
//
// R16: pair-table gather. The LSU/crossbar budget (gather LDS + seg LDS +
// STG) matches wallclock, so only reducing gather phases helps. Per image
// build pairs[s][i] = (l_i, l_{i+1}), i=0..3, row stride 40B (float2 index
// 5s+i, gcd(5,16)=1 -> uniform bank-pairs). Each thread's 4 floats are two
// LDS.64 + (r in {2,4} only) one LDS.32:
//   r=0: P1=pr[5s0+0] P2=pr[5s0+2]            v=(P1.x,P1.y,P2.x,P2.y)
//   r=1: P1=pr[5s0+1] P2=pr[5s0+3]            v=(P1.x,P1.y,P2.x,P2.y)
//   r=2: P1=pr[5s0+2] P2=pr[5s0+3] S=l0(s1)   v=(P1.x,P1.y,P2.y,S)
//   r=3: P1=pr[5s0+3] P2=pr[5s1+0]            v=(P1.x,P1.y,P2.x,P2.y)
//   r=4: P1=pr[5s0+3] P2=pr[5s1+0] S=l2(s1)   v=(P1.y,P2.x,P2.y,S)
// Single-wave persistent blocks (880 @ 6/SM), balanced 19/18-unit split,
// seg TMA into 2 rolling 7-unit buffers (one mid-kernel syncthreads).

#define N_IMG 16
#define SIZE  512
#define N_SP  512
#define WAY   5
#define PIX_PER_IMG    (SIZE * SIZE)            // 262144
#define VEC_PER_IMG    (PIX_PER_IMG * WAY / 4)  // 327680 float4
#define LOGITS_PER_IMG (N_SP * WAY)             // 2560 floats

#define THREADS 320
#define BLOCKS_PER_IMG 55                       // 880 blocks <= 888 slots
#define UNIT_PIX   256
#define UNIT_VEC   320
#define CHUNK_UNITS 7
#define BIG_BLOCKS 34                           // 1024 = 55*18 + 34

#define PAIR_FLOATS 10                          // row stride: 10 floats = 40B
#define PAIR_TABLE_FLOATS (N_SP * PAIR_FLOATS)  // 5120 floats = 20KB

__device__ __forceinline__ uint32_t smem_u32(const void* p) {
    uint32_t a;
    asm("{ .reg .u64 t; cvta.to.shared.u64 t, %1; cvt.u32.u64 %0, t; }"
        : "=r"(a) : "l"(p));
    return a;
}

__device__ __forceinline__ void mbar_wait0(uint32_t mb) {
    uint32_t done;
    asm volatile(
        "{\n\t"
        ".reg .pred p;\n\t"
        "mbarrier.try_wait.parity.acquire.cta.shared::cta.b64 p, [%1], 0;\n\t"
        "selp.b32 %0, 1, 0, p;\n\t"
        "}" : "=r"(done) : "r"(mb) : "memory");
    if (!done) {
        asm volatile(
            "{\n\t"
            ".reg .pred P1;\n\t"
            "WL_%=:\n\t"
            "mbarrier.try_wait.parity.acquire.cta.shared::cta.b64 P1, [%0], 0, 0x989680;\n\t"
            "@P1 bra.uni WD_%=;\n\t"
            "bra.uni WL_%=;\n\t"
            "WD_%=:\n\t"
            "}" :: "r"(mb) : "memory");
    }
}

__global__ void __launch_bounds__(THREADS, 6)
sp_gather_kernel16(const float* __restrict__ logits,
                   const int* __restrict__ seg,
                   float4* __restrict__ out)
{
    __shared__ __align__(16) float    s_pairs[PAIR_TABLE_FLOATS];   // 20KB
    __shared__ __align__(16) int      s_segA[CHUNK_UNITS * UNIT_PIX]; // 7KB
    __shared__ __align__(16) int      s_segB[CHUNK_UNITS * UNIT_PIX]; // 7KB
    __shared__ __align__(8)  uint64_t s_mbar[3];

    const int img = blockIdx.y;
    const int blk = blockIdx.x;
    const int tid = threadIdx.x;

    const int big    = (blk < BIG_BLOCKS);
    const int ucount = 18 + big;                               // 18 or 19
    const int ustart = 18 * blk + (big ? blk : BIG_BLOCKS);
    const int u2     = ucount - 2 * CHUNK_UNITS;               // 4 or 5

    if (tid == 0) {
#pragma unroll
        for (int c = 0; c < 3; ++c) {
            uint32_t mb = smem_u32(&s_mbar[c]);
            asm volatile("mbarrier.init.shared.b64 [%0], 1;" :: "r"(mb) : "memory");
        }
    }
    __syncthreads();

    const int* seg_img = seg + (size_t)img * PIX_PER_IMG;

    // Issue chunk0 + chunk1 seg TMA loads.
    if (tid == 0) {
        uint32_t mb0 = smem_u32(&s_mbar[0]);
        asm volatile("mbarrier.arrive.expect_tx.shared.b64 _, [%0], %1;"
                     :: "r"(mb0), "n"(CHUNK_UNITS * UNIT_PIX * 4) : "memory");
        asm volatile(
            "cp.async.bulk.shared::cta.global.mbarrier::complete_tx::bytes "
            "[%0], [%1], %2, [%3];"
            :: "r"(smem_u32(s_segA)),
               "l"(seg_img + (size_t)ustart * UNIT_PIX),
               "n"(CHUNK_UNITS * UNIT_PIX * 4), "r"(mb0) : "memory");

        uint32_t mb1 = smem_u32(&s_mbar[1]);
        asm volatile("mbarrier.arrive.expect_tx.shared.b64 _, [%0], %1;"
                     :: "r"(mb1), "n"(CHUNK_UNITS * UNIT_PIX * 4) : "memory");
        asm volatile(
            "cp.async.bulk.shared::cta.global.mbarrier::complete_tx::bytes "
            "[%0], [%1], %2, [%3];"
            :: "r"(smem_u32(s_segB)),
               "l"(seg_img + (size_t)(ustart + CHUNK_UNITS) * UNIT_PIX),
               "n"(CHUNK_UNITS * UNIT_PIX * 4), "r"(mb1) : "memory");
    }

    // Build pair table from global logits (L2/L1-resident, coalesced).
    // Thread t handles floats j = 8t .. 8t+7 (2560 / 320 = 8).
    {
        const float4* lg = (const float4*)(logits + (size_t)img * LOGITS_PER_IMG);
        float4 a = __ldg(lg + tid * 2);
        float4 b = __ldg(lg + tid * 2 + 1);
        float lv[8] = {a.x, a.y, a.z, a.w, b.x, b.y, b.z, b.w};
        int j = tid * 8;
#pragma unroll
        for (int q = 0; q < 8; ++q, ++j) {
            int s = j / 5;
            int k = j - 5 * s;
            // pair(k).x at float offset s*10 + 2k  (k=4 slot unused by reads)
            s_pairs[s * PAIR_FLOATS + 2 * k] = lv[q];
            // pair(k-1).y at offset s*10 + 2k - 1
            if (k >= 1) s_pairs[s * PAIR_FLOATS + 2 * k - 1] = lv[q];
        }
    }
    __syncthreads();   // table visible to all

    // Per-thread constants.
    const int floc = tid << 2;            // 0..1276 within a unit
    const int p0   = floc / 5;            // 0..255
    const int r    = floc - 5 * p0;       // 0..4, constant per thread
    const bool need_s1 = (r >= 2);
    const bool c24 = (r == 2) || (r == 4);
    const bool c4  = (r == 4);
    const int  k1  = (r <= 3) ? r : 3;            // P1 pair index (in s0)
    const int  k2  = (r == 0) ? 2 : 3;            // P2 pair index when in s0
    const bool p2_in_s1 = (r >= 3);
    const int  koffS = (r == 2) ? 0 : 4;          // S float offset within s1 row

    const float2* pr = (const float2*)s_pairs;
    float4* out_units = out + (size_t)img * VEC_PER_IMG
                            + (size_t)ustart * UNIT_VEC + tid;

#define UNIT_BODY(SSEG, GIDX)                                              \
    do {                                                                    \
        const int* _sg = (SSEG);                                            \
        int _s0 = _sg[p0];                                                  \
        int _s1 = need_s1 ? _sg[p0 + 1] : 0;                                \
        int _i1 = _s0 * 5 + k1;                                             \
        int _i2 = p2_in_s1 ? (_s1 * 5) : (_s0 * 5 + k2);                    \
        float2 _P1 = pr[_i1];                                               \
        float2 _P2 = pr[_i2];                                               \
        float _S = 0.0f;                                                    \
        if (c24) _S = s_pairs[_s1 * PAIR_FLOATS + koffS];                   \
        float _v0 = c4 ? _P1.y : _P1.x;                                     \
        float _v1 = c4 ? _P2.x : _P1.y;                                     \
        float _v2 = c24 ? _P2.y : _P2.x;                                    \
        float _v3 = c24 ? _S : _P2.y;                                       \
        out_units[(size_t)(GIDX) * UNIT_VEC] = make_float4(_v0, _v1, _v2, _v3); \
    } while (0)

    // Chunk 0 (units 0..6) from bufA.
    mbar_wait0(smem_u32(&s_mbar[0]));
#pragma unroll
    for (int uu = 0; uu < CHUNK_UNITS; ++uu)
        UNIT_BODY(&s_segA[uu * UNIT_PIX], uu);

    // All threads done reading bufA -> safe to refill it with chunk 2.
    __syncthreads();
    if (tid == 0) {
        uint32_t bytes = (uint32_t)u2 * UNIT_PIX * 4;
        uint32_t mb2 = smem_u32(&s_mbar[2]);
        asm volatile("mbarrier.arrive.expect_tx.shared.b64 _, [%0], %1;"
                     :: "r"(mb2), "r"(bytes) : "memory");
        asm volatile(
            "cp.async.bulk.shared::cta.global.mbarrier::complete_tx::bytes "
            "[%0], [%1], %2, [%3];"
            :: "r"(smem_u32(s_segA)),
               "l"(seg_img + (size_t)(ustart + 2 * CHUNK_UNITS) * UNIT_PIX),
               "r"(bytes), "r"(mb2) : "memory");
    }

    // Chunk 1 (units 7..13) from bufB (TMA into A overlaps this).
    mbar_wait0(smem_u32(&s_mbar[1]));
#pragma unroll
    for (int uu = 0; uu < CHUNK_UNITS; ++uu)
        UNIT_BODY(&s_segB[uu * UNIT_PIX], CHUNK_UNITS + uu);

    // Chunk 2 (units 14..ucount-1) from bufA.
    mbar_wait0(smem_u32(&s_mbar[2]));
#pragma unroll 1
    for (int uu = 0; uu < u2; ++uu)
        UNIT_BODY(&s_segA[uu * UNIT_PIX], 2 * CHUNK_UNITS + uu);

#undef UNIT_BODY
}

extern "C" void kernel_launch(void* const* d_in, const int* in_sizes, int n_in,
                              void* d_out, int out_size)
{
    const float* logits = (const float*)d_in[0];
    const int*   seg    = (const int*)d_in[1];
    float4*      out    = (float4*)d_out;

    dim3 grid(BLOCKS_PER_IMG, N_IMG);
    sp_gather_kernel16<<<grid, THREADS>>>(logits, seg, out);
}